// round 2
// baseline (speedup 1.0000x reference)
#include <cuda_runtime.h>
#include <math.h>

#define BB 2
#define SS 2048
#define EE 1024
#define HH 16
#define DHH 64
#define MM (BB*SS)

// Scratch (no cudaMalloc allowed): head-split q,k,v [B,H,S,DH] + merged attn out [B,S,E]
__device__ float g_q[BB*HH*SS*DHH];
__device__ float g_k[BB*HH*SS*DHH];
__device__ float g_v[BB*HH*SS*DHH];
__device__ float g_attn[BB*SS*EE];

// ---------------------------------------------------------------------------
// SGEMM: out = X[M,E] @ W[E,E] + bias[E]
// 64x64 block tile, 256 threads (16x16), 4x4 register tile, k-chunk 16.
// split!=0: write head-split layout [B,H,S,DH]; else plain [M,E].
// ---------------------------------------------------------------------------
__global__ __launch_bounds__(256) void proj_kernel(
    const float* __restrict__ X, const float* __restrict__ W,
    const float* __restrict__ bias, float* __restrict__ out, int split)
{
    __shared__ float a_s[16][68];  // [k][m] transposed
    __shared__ float b_s[16][68];  // [k][n]

    const int tid = threadIdx.x;
    const int tx = tid & 15, ty = tid >> 4;
    const int n0 = blockIdx.x * 64;
    const int m0 = blockIdx.y * 64;

    float acc[4][4] = {};

    for (int k0 = 0; k0 < EE; k0 += 16) {
        #pragma unroll
        for (int r = 0; r < 4; r++) {
            int idx = tid + r * 256;
            int ml = idx >> 4, kl = idx & 15;
            a_s[kl][ml] = X[(size_t)(m0 + ml) * EE + k0 + kl];
        }
        #pragma unroll
        for (int r = 0; r < 4; r++) {
            int idx = tid + r * 256;
            int kl = idx >> 6, nl = idx & 63;
            b_s[kl][nl] = W[(size_t)(k0 + kl) * EE + n0 + nl];
        }
        __syncthreads();
        #pragma unroll
        for (int k = 0; k < 16; k++) {
            float av[4], bv[4];
            #pragma unroll
            for (int i = 0; i < 4; i++) av[i] = a_s[k][ty * 4 + i];
            #pragma unroll
            for (int j = 0; j < 4; j++) bv[j] = b_s[k][tx * 4 + j];
            #pragma unroll
            for (int i = 0; i < 4; i++)
                #pragma unroll
                for (int j = 0; j < 4; j++)
                    acc[i][j] += av[i] * bv[j];
        }
        __syncthreads();
    }

    float bv[4];
    #pragma unroll
    for (int j = 0; j < 4; j++) bv[j] = bias[n0 + tx * 4 + j];

    if (split) {
        // m = b*S + s ; n = h*DH + d  ->  out[((b*H+h)*S + s)*DH + d]
        // tile is 64 rows (within one batch since S%64==0) and 64 cols (= one head)
        const int bb = m0 / SS;
        const int hh = n0 / DHH;
        const int sb = m0 % SS;
        float* dst = out + ((size_t)(bb * HH + hh) * SS) * DHH;
        #pragma unroll
        for (int i = 0; i < 4; i++)
            #pragma unroll
            for (int j = 0; j < 4; j++)
                dst[(size_t)(sb + ty * 4 + i) * DHH + tx * 4 + j] = acc[i][j] + bv[j];
    } else {
        #pragma unroll
        for (int i = 0; i < 4; i++)
            #pragma unroll
            for (int j = 0; j < 4; j++)
                out[(size_t)(m0 + ty * 4 + i) * EE + n0 + tx * 4 + j] = acc[i][j] + bv[j];
    }
}

// ---------------------------------------------------------------------------
// Flash attention: one block per (b, h, 64-row q tile). 32-key tiles.
// Online softmax, fp32 accumulation. Writes merged-heads layout [B,S,E].
// ---------------------------------------------------------------------------
__global__ __launch_bounds__(256) void attn_kernel(
    const int* __restrict__ mask, float* __restrict__ out)
{
    __shared__ float q_s[64][65];    // [row][d]
    __shared__ float kt_s[64][33];   // [d][key]  (transposed)
    __shared__ float v_s[32][65];    // [key][d]
    __shared__ float p_s[64][33];    // scores -> probs [row][key]
    __shared__ float m_s[64], l_s[64], scale_s[64];
    __shared__ int   mk_s[32];

    const int tid = threadIdx.x;
    const int bb = blockIdx.z, hh = blockIdx.y;
    const int q0 = blockIdx.x * 64;

    const float* Q = g_q + ((size_t)(bb * HH + hh) * SS) * DHH;
    const float* K = g_k + ((size_t)(bb * HH + hh) * SS) * DHH;
    const float* V = g_v + ((size_t)(bb * HH + hh) * SS) * DHH;

    // load Q tile (64x64)
    #pragma unroll
    for (int r = 0; r < 16; r++) {
        int idx = tid + r * 256;
        int row = idx >> 6, d = idx & 63;
        q_s[row][d] = Q[(size_t)(q0 + row) * DHH + d];
    }
    if (tid < 64) { m_s[tid] = -1e30f; l_s[tid] = 0.f; }

    // thread mappings
    const int tx = tid & 15, ty = tid >> 4;  // PV/output: rows ty*4.., dims tx*4..
    const int sx = tid & 7,  sy = tid >> 3;  // score: cols sx*4.., rows sy*2..
    const int rrow = tid >> 2, rq = tid & 3; // softmax: row rrow, cols rq*8..

    float o_acc[4][4] = {};
    __syncthreads();

    for (int kt = 0; kt < SS; kt += 32) {
        // load K tile transposed + V tile (32 keys x 64 d = 2048 elems each)
        #pragma unroll
        for (int r = 0; r < 8; r++) {
            int idx = tid + r * 256;
            int key = idx >> 6, d = idx & 63;
            kt_s[d][key] = K[(size_t)(kt + key) * DHH + d];
            v_s[key][d]  = V[(size_t)(kt + key) * DHH + d];
        }
        if (tid < 32) mk_s[tid] = mask[bb * SS + kt + tid];
        __syncthreads();

        // scores: 64 rows x 32 keys, thread = 2x4 subtile
        float sacc[2][4] = {};
        #pragma unroll
        for (int d = 0; d < 64; d++) {
            float qv[2], kv[4];
            qv[0] = q_s[sy * 2 + 0][d];
            qv[1] = q_s[sy * 2 + 1][d];
            #pragma unroll
            for (int j = 0; j < 4; j++) kv[j] = kt_s[d][sx * 4 + j];
            #pragma unroll
            for (int i = 0; i < 2; i++)
                #pragma unroll
                for (int j = 0; j < 4; j++)
                    sacc[i][j] += qv[i] * kv[j];
        }
        #pragma unroll
        for (int i = 0; i < 2; i++)
            #pragma unroll
            for (int j = 0; j < 4; j++) {
                float v = sacc[i][j] * 0.125f;           // 1/sqrt(64)
                if (mk_s[sx * 4 + j] == 0) v = -1e9f;
                p_s[sy * 2 + i][sx * 4 + j] = v;
            }
        __syncthreads();

        // online softmax: 4 threads per row, 8 cols each
        float vals[8];
        float tmax = -1e30f;
        #pragma unroll
        for (int c = 0; c < 8; c++) {
            vals[c] = p_s[rrow][rq * 8 + c];
            tmax = fmaxf(tmax, vals[c]);
        }
        tmax = fmaxf(tmax, __shfl_xor_sync(0xffffffffu, tmax, 1));
        tmax = fmaxf(tmax, __shfl_xor_sync(0xffffffffu, tmax, 2));
        const float m_old = m_s[rrow];
        const float m_new = fmaxf(m_old, tmax);
        float tsum = 0.f;
        #pragma unroll
        for (int c = 0; c < 8; c++) {
            float p = __expf(vals[c] - m_new);
            p_s[rrow][rq * 8 + c] = p;
            tsum += p;
        }
        tsum += __shfl_xor_sync(0xffffffffu, tsum, 1);
        tsum += __shfl_xor_sync(0xffffffffu, tsum, 2);
        if (rq == 0) {
            const float sc = __expf(m_old - m_new);
            l_s[rrow] = l_s[rrow] * sc + tsum;
            m_s[rrow] = m_new;
            scale_s[rrow] = sc;
        }
        __syncthreads();

        // rescale running output, accumulate P@V
        float rs[4];
        #pragma unroll
        for (int i = 0; i < 4; i++) rs[i] = scale_s[ty * 4 + i];
        #pragma unroll
        for (int i = 0; i < 4; i++)
            #pragma unroll
            for (int j = 0; j < 4; j++)
                o_acc[i][j] *= rs[i];

        #pragma unroll
        for (int k = 0; k < 32; k++) {
            float pv[4], vv[4];
            #pragma unroll
            for (int i = 0; i < 4; i++) pv[i] = p_s[ty * 4 + i][k];
            #pragma unroll
            for (int j = 0; j < 4; j++) vv[j] = v_s[k][tx * 4 + j];
            #pragma unroll
            for (int i = 0; i < 4; i++)
                #pragma unroll
                for (int j = 0; j < 4; j++)
                    o_acc[i][j] += pv[i] * vv[j];
        }
        __syncthreads();
    }

    // finalize: divide by l, write merged-heads [B,S,E]
    float li[4];
    #pragma unroll
    for (int i = 0; i < 4; i++) li[i] = 1.0f / l_s[ty * 4 + i];
    #pragma unroll
    for (int i = 0; i < 4; i++)
        #pragma unroll
        for (int j = 0; j < 4; j++)
            out[(size_t)(bb * SS + q0 + ty * 4 + i) * EE + hh * DHH + tx * 4 + j] =
                o_acc[i][j] * li[i];
}

// ---------------------------------------------------------------------------
extern "C" void kernel_launch(void* const* d_in, const int* in_sizes, int n_in,
                              void* d_out, int out_size)
{
    const float* query = (const float*)d_in[0];
    const float* key   = (const float*)d_in[1];
    const float* value = (const float*)d_in[2];
    const int*   mask  = (const int*)  d_in[3];
    const float* Wq = (const float*)d_in[4];
    const float* bq = (const float*)d_in[5];
    const float* Wk = (const float*)d_in[6];
    const float* bk = (const float*)d_in[7];
    const float* Wv = (const float*)d_in[8];
    const float* bv = (const float*)d_in[9];
    const float* Wo = (const float*)d_in[10];
    const float* bo = (const float*)d_in[11];
    float* out = (float*)d_out;

    float *gq, *gk, *gv, *ga;
    cudaGetSymbolAddress((void**)&gq, g_q);
    cudaGetSymbolAddress((void**)&gk, g_k);
    cudaGetSymbolAddress((void**)&gv, g_v);
    cudaGetSymbolAddress((void**)&ga, g_attn);

    dim3 pgrid(EE / 64, MM / 64);        // (16, 64)
    proj_kernel<<<pgrid, 256>>>(query, Wq, bq, gq, 1);
    proj_kernel<<<pgrid, 256>>>(key,   Wk, bk, gk, 1);
    proj_kernel<<<pgrid, 256>>>(value, Wv, bv, gv, 1);

    dim3 agrid(SS / 64, HH, BB);         // (32, 16, 2)
    attn_kernel<<<agrid, 256>>>(mask, ga);

    proj_kernel<<<pgrid, 256>>>(ga, Wo, bo, out, 0);
}

// round 5
// speedup vs baseline: 1.4357x; 1.4357x over previous
#include <cuda_runtime.h>
#include <cstdint>
#include <math.h>

#define BB 2
#define SS 2048
#define EE 1024
#define HH 16
#define DHH 64
#define MM (BB*SS)

// Scratch (no cudaMalloc allowed)
__device__ float g_q[BB*HH*SS*DHH];
__device__ float g_k[BB*HH*SS*DHH];
__device__ float g_v[BB*HH*SS*DHH];
__device__ float g_attn[BB*SS*EE];
__device__ float g_wt[4*EE*EE];      // transposed weights [N][K]

__device__ __forceinline__ float tf32r(float x) {
    float y;
    asm("cvt.rna.tf32.f32 %0, %1;" : "=f"(y) : "f"(x));
    return y;
}

// m16n8k8 tf32 mma.sync (standard sm_80+ PTX — works on .target sm_103)
#define MMA_TF32(c, a, b) \
    asm volatile("mma.sync.aligned.m16n8k8.row.col.f32.tf32.tf32.f32 " \
        "{%0,%1,%2,%3}, {%4,%5,%6,%7}, {%8,%9}, {%0,%1,%2,%3};" \
        : "+f"((c)[0]), "+f"((c)[1]), "+f"((c)[2]), "+f"((c)[3]) \
        : "r"(__float_as_uint((a)[0])), "r"(__float_as_uint((a)[1])), \
          "r"(__float_as_uint((a)[2])), "r"(__float_as_uint((a)[3])), \
          "r"(__float_as_uint((b)[0])), "r"(__float_as_uint((b)[1])))

// ---------------------------------------------------------------------------
// Weight transpose: Wt[n][k] = W[k][n]   (E x E)
// ---------------------------------------------------------------------------
__global__ __launch_bounds__(256) void transpose_kernel(
    const float* __restrict__ W, float* __restrict__ Wt)
{
    __shared__ float t[32][33];
    const int bx = blockIdx.x * 32;  // n
    const int by = blockIdx.y * 32;  // k
    const int x = threadIdx.x, y = threadIdx.y;
    #pragma unroll
    for (int r = 0; r < 4; r++)
        t[y + r * 8][x] = W[(size_t)(by + y + r * 8) * EE + bx + x];
    __syncthreads();
    #pragma unroll
    for (int r = 0; r < 4; r++)
        Wt[(size_t)(bx + y + r * 8) * EE + by + x] = t[x][y + r * 8];
}

// ---------------------------------------------------------------------------
// HMMA tf32 GEMM: out = X[M,E] @ W[E,E] + bias  (Wt pre-transposed: Wt[n][k])
// Block tile 128x128, 8 warps (2x4), warp tile 64x32, k-chunk 32,
// reg-prefetch single-buffer smem pipeline.
// split!=0: write head-split [B,H,S,DH]; else [M,E].
// ---------------------------------------------------------------------------
__global__ __launch_bounds__(256) void gemm_mma_kernel(
    const float* __restrict__ X, const float* __restrict__ Wt,
    const float* __restrict__ bias, float* __restrict__ out, int split)
{
    __shared__ float As[128][36];   // [m][k], pad 36: frag loads conflict-free
    __shared__ float Bs[128][36];   // [n][k]

    const int tid = threadIdx.x;
    const int wid = tid >> 5, lane = tid & 31;
    const int g = lane >> 2, t4 = lane & 3;
    const int wm = wid >> 2, wn = wid & 3;     // warp grid 2 (m) x 4 (n)
    const int n0 = blockIdx.x * 128;
    const int m0 = blockIdx.y * 128;

    float c[4][4][4];
    #pragma unroll
    for (int mi = 0; mi < 4; mi++)
        #pragma unroll
        for (int ni = 0; ni < 4; ni++)
            #pragma unroll
            for (int e = 0; e < 4; e++) c[mi][ni][e] = 0.f;

    // prefetch chunk 0 into registers
    float4 Ar[4], Br[4];
    #pragma unroll
    for (int r = 0; r < 4; r++) {
        const int id = r * 256 + tid;
        const int row = id >> 3, c4 = id & 7;
        Ar[r] = *(const float4*)(X  + (size_t)(m0 + row) * EE + c4 * 4);
        Br[r] = *(const float4*)(Wt + (size_t)(n0 + row) * EE + c4 * 4);
    }

    for (int t = 0; t < EE / 32; t++) {
        // stage regs -> smem (tf32-rounded)
        #pragma unroll
        for (int r = 0; r < 4; r++) {
            const int id = r * 256 + tid;
            const int row = id >> 3, c4 = id & 7;
            float4 va = Ar[r];
            va.x = tf32r(va.x); va.y = tf32r(va.y); va.z = tf32r(va.z); va.w = tf32r(va.w);
            *(float4*)&As[row][c4 * 4] = va;
            float4 vb = Br[r];
            vb.x = tf32r(vb.x); vb.y = tf32r(vb.y); vb.z = tf32r(vb.z); vb.w = tf32r(vb.w);
            *(float4*)&Bs[row][c4 * 4] = vb;
        }
        __syncthreads();

        // prefetch next chunk (overlaps with compute below)
        if (t + 1 < EE / 32) {
            const int k0 = (t + 1) * 32;
            #pragma unroll
            for (int r = 0; r < 4; r++) {
                const int id = r * 256 + tid;
                const int row = id >> 3, c4 = id & 7;
                Ar[r] = *(const float4*)(X  + (size_t)(m0 + row) * EE + k0 + c4 * 4);
                Br[r] = *(const float4*)(Wt + (size_t)(n0 + row) * EE + k0 + c4 * 4);
            }
        }

        // compute: 4 k-steps of 8
        #pragma unroll
        for (int kk = 0; kk < 32; kk += 8) {
            float a[4][4], b[4][2];
            #pragma unroll
            for (int mi = 0; mi < 4; mi++) {
                const int row = wm * 64 + mi * 16;
                a[mi][0] = As[row + g][kk + t4];
                a[mi][1] = As[row + g + 8][kk + t4];
                a[mi][2] = As[row + g][kk + t4 + 4];
                a[mi][3] = As[row + g + 8][kk + t4 + 4];
            }
            #pragma unroll
            for (int ni = 0; ni < 4; ni++) {
                const int col = wn * 32 + ni * 8 + g;
                b[ni][0] = Bs[col][kk + t4];
                b[ni][1] = Bs[col][kk + t4 + 4];
            }
            #pragma unroll
            for (int mi = 0; mi < 4; mi++)
                #pragma unroll
                for (int ni = 0; ni < 4; ni++)
                    MMA_TF32(c[mi][ni], a[mi], b[ni]);
        }
        __syncthreads();
    }

    // epilogue: c0,c1 -> (row, cb..cb+1), c2,c3 -> (row+8, cb..cb+1)
    #pragma unroll
    for (int mi = 0; mi < 4; mi++) {
        #pragma unroll
        for (int ni = 0; ni < 4; ni++) {
            const int r0 = m0 + wm * 64 + mi * 16 + g;
            const int cb = n0 + wn * 32 + ni * 8 + t4 * 2;
            const float bx = bias[cb], by = bias[cb + 1];
            #pragma unroll
            for (int half = 0; half < 2; half++) {
                const int r = r0 + half * 8;
                float2 v;
                v.x = c[mi][ni][half * 2 + 0] + bx;
                v.y = c[mi][ni][half * 2 + 1] + by;
                if (split) {
                    const int bbi = r >> 11, s = r & (SS - 1);
                    const int h = cb >> 6, d = cb & 63;
                    *(float2*)(out + ((size_t)(bbi * HH + h) * SS + s) * DHH + d) = v;
                } else {
                    *(float2*)(out + (size_t)r * EE + cb) = v;
                }
            }
        }
    }
}

// ---------------------------------------------------------------------------
// Flash attention (unchanged from passing R2 kernel)
// ---------------------------------------------------------------------------
__global__ __launch_bounds__(256) void attn_kernel(
    const int* __restrict__ mask, float* __restrict__ out)
{
    __shared__ float q_s[64][65];
    __shared__ float kt_s[64][33];
    __shared__ float v_s[32][65];
    __shared__ float p_s[64][33];
    __shared__ float m_s[64], l_s[64], scale_s[64];
    __shared__ int   mk_s[32];

    const int tid = threadIdx.x;
    const int bb = blockIdx.z, hh = blockIdx.y;
    const int q0 = blockIdx.x * 64;

    const float* Q = g_q + ((size_t)(bb * HH + hh) * SS) * DHH;
    const float* K = g_k + ((size_t)(bb * HH + hh) * SS) * DHH;
    const float* V = g_v + ((size_t)(bb * HH + hh) * SS) * DHH;

    #pragma unroll
    for (int r = 0; r < 16; r++) {
        int idx = tid + r * 256;
        int row = idx >> 6, d = idx & 63;
        q_s[row][d] = Q[(size_t)(q0 + row) * DHH + d];
    }
    if (tid < 64) { m_s[tid] = -1e30f; l_s[tid] = 0.f; }

    const int tx = tid & 15, ty = tid >> 4;
    const int sx = tid & 7,  sy = tid >> 3;
    const int rrow = tid >> 2, rq = tid & 3;

    float o_acc[4][4] = {};
    __syncthreads();

    for (int kt = 0; kt < SS; kt += 32) {
        #pragma unroll
        for (int r = 0; r < 8; r++) {
            int idx = tid + r * 256;
            int key = idx >> 6, d = idx & 63;
            kt_s[d][key] = K[(size_t)(kt + key) * DHH + d];
            v_s[key][d]  = V[(size_t)(kt + key) * DHH + d];
        }
        if (tid < 32) mk_s[tid] = mask[bb * SS + kt + tid];
        __syncthreads();

        float sacc[2][4] = {};
        #pragma unroll
        for (int d = 0; d < 64; d++) {
            float qv[2], kv[4];
            qv[0] = q_s[sy * 2 + 0][d];
            qv[1] = q_s[sy * 2 + 1][d];
            #pragma unroll
            for (int j = 0; j < 4; j++) kv[j] = kt_s[d][sx * 4 + j];
            #pragma unroll
            for (int i = 0; i < 2; i++)
                #pragma unroll
                for (int j = 0; j < 4; j++)
                    sacc[i][j] += qv[i] * kv[j];
        }
        #pragma unroll
        for (int i = 0; i < 2; i++)
            #pragma unroll
            for (int j = 0; j < 4; j++) {
                float v = sacc[i][j] * 0.125f;
                if (mk_s[sx * 4 + j] == 0) v = -1e9f;
                p_s[sy * 2 + i][sx * 4 + j] = v;
            }
        __syncthreads();

        float vals[8];
        float tmax = -1e30f;
        #pragma unroll
        for (int c = 0; c < 8; c++) {
            vals[c] = p_s[rrow][rq * 8 + c];
            tmax = fmaxf(tmax, vals[c]);
        }
        tmax = fmaxf(tmax, __shfl_xor_sync(0xffffffffu, tmax, 1));
        tmax = fmaxf(tmax, __shfl_xor_sync(0xffffffffu, tmax, 2));
        const float m_old = m_s[rrow];
        const float m_new = fmaxf(m_old, tmax);
        float tsum = 0.f;
        #pragma unroll
        for (int c = 0; c < 8; c++) {
            float p = __expf(vals[c] - m_new);
            p_s[rrow][rq * 8 + c] = p;
            tsum += p;
        }
        tsum += __shfl_xor_sync(0xffffffffu, tsum, 1);
        tsum += __shfl_xor_sync(0xffffffffu, tsum, 2);
        if (rq == 0) {
            const float sc = __expf(m_old - m_new);
            l_s[rrow] = l_s[rrow] * sc + tsum;
            m_s[rrow] = m_new;
            scale_s[rrow] = sc;
        }
        __syncthreads();

        float rs[4];
        #pragma unroll
        for (int i = 0; i < 4; i++) rs[i] = scale_s[ty * 4 + i];
        #pragma unroll
        for (int i = 0; i < 4; i++)
            #pragma unroll
            for (int j = 0; j < 4; j++)
                o_acc[i][j] *= rs[i];

        #pragma unroll
        for (int k = 0; k < 32; k++) {
            float pv[4], vv[4];
            #pragma unroll
            for (int i = 0; i < 4; i++) pv[i] = p_s[ty * 4 + i][k];
            #pragma unroll
            for (int j = 0; j < 4; j++) vv[j] = v_s[k][tx * 4 + j];
            #pragma unroll
            for (int i = 0; i < 4; i++)
                #pragma unroll
                for (int j = 0; j < 4; j++)
                    o_acc[i][j] += pv[i] * vv[j];
        }
        __syncthreads();
    }

    float li[4];
    #pragma unroll
    for (int i = 0; i < 4; i++) li[i] = 1.0f / l_s[ty * 4 + i];
    #pragma unroll
    for (int i = 0; i < 4; i++)
        #pragma unroll
        for (int j = 0; j < 4; j++)
            out[(size_t)(bb * SS + q0 + ty * 4 + i) * EE + hh * DHH + tx * 4 + j] =
                o_acc[i][j] * li[i];
}

// ---------------------------------------------------------------------------
extern "C" void kernel_launch(void* const* d_in, const int* in_sizes, int n_in,
                              void* d_out, int out_size)
{
    const float* query = (const float*)d_in[0];
    const float* key   = (const float*)d_in[1];
    const float* value = (const float*)d_in[2];
    const int*   mask  = (const int*)  d_in[3];
    const float* Wq = (const float*)d_in[4];
    const float* bq = (const float*)d_in[5];
    const float* Wk = (const float*)d_in[6];
    const float* bk = (const float*)d_in[7];
    const float* Wv = (const float*)d_in[8];
    const float* bv = (const float*)d_in[9];
    const float* Wo = (const float*)d_in[10];
    const float* bo = (const float*)d_in[11];
    float* out = (float*)d_out;

    float *gq, *gk, *gv, *ga, *gw;
    cudaGetSymbolAddress((void**)&gq, g_q);
    cudaGetSymbolAddress((void**)&gk, g_k);
    cudaGetSymbolAddress((void**)&gv, g_v);
    cudaGetSymbolAddress((void**)&ga, g_attn);
    cudaGetSymbolAddress((void**)&gw, g_wt);

    dim3 tgrid(EE / 32, EE / 32);
    dim3 tblk(32, 8);
    transpose_kernel<<<tgrid, tblk>>>(Wq, gw + 0 * (size_t)EE * EE);
    transpose_kernel<<<tgrid, tblk>>>(Wk, gw + 1 * (size_t)EE * EE);
    transpose_kernel<<<tgrid, tblk>>>(Wv, gw + 2 * (size_t)EE * EE);
    transpose_kernel<<<tgrid, tblk>>>(Wo, gw + 3 * (size_t)EE * EE);

    dim3 ggrid(EE / 128, MM / 128);    // (8, 32)
    gemm_mma_kernel<<<ggrid, 256>>>(query, gw + 0 * (size_t)EE * EE, bq, gq, 1);
    gemm_mma_kernel<<<ggrid, 256>>>(key,   gw + 1 * (size_t)EE * EE, bk, gk, 1);
    gemm_mma_kernel<<<ggrid, 256>>>(value, gw + 2 * (size_t)EE * EE, bv, gv, 1);

    dim3 agrid(SS / 64, HH, BB);       // (32, 16, 2)
    attn_kernel<<<agrid, 256>>>(mask, ga);

    gemm_mma_kernel<<<ggrid, 256>>>(ga, gw + 3 * (size_t)EE * EE, bo, out, 0);
}

// round 6
// speedup vs baseline: 3.1137x; 2.1688x over previous
#include <cuda_runtime.h>
#include <cstdint>
#include <math.h>

#define BB 2
#define SS 2048
#define EE 1024
#define HH 16
#define DHH 64
#define MM (BB*SS)

// Scratch (no cudaMalloc allowed)
__device__ float g_q[BB*HH*SS*DHH];
__device__ float g_k[BB*HH*SS*DHH];
__device__ float g_v[BB*HH*SS*DHH];
__device__ float g_attn[BB*SS*EE];
__device__ float g_wt[4*EE*EE];      // transposed weights [N][K]

__device__ __forceinline__ float tf32r(float x) {
    float y;
    asm("cvt.rna.tf32.f32 %0, %1;" : "=f"(y) : "f"(x));
    return y;
}

// m16n8k8 tf32 mma.sync (standard sm_80+ PTX — works on .target sm_103)
#define MMA_TF32(c, a, b) \
    asm volatile("mma.sync.aligned.m16n8k8.row.col.f32.tf32.tf32.f32 " \
        "{%0,%1,%2,%3}, {%4,%5,%6,%7}, {%8,%9}, {%0,%1,%2,%3};" \
        : "+f"((c)[0]), "+f"((c)[1]), "+f"((c)[2]), "+f"((c)[3]) \
        : "r"(__float_as_uint((a)[0])), "r"(__float_as_uint((a)[1])), \
          "r"(__float_as_uint((a)[2])), "r"(__float_as_uint((a)[3])), \
          "r"(__float_as_uint((b)[0])), "r"(__float_as_uint((b)[1])))

// ---------------------------------------------------------------------------
// Weight transpose: Wt[n][k] = W[k][n]   (E x E)
// ---------------------------------------------------------------------------
__global__ __launch_bounds__(256) void transpose_kernel(
    const float* __restrict__ W, float* __restrict__ Wt)
{
    __shared__ float t[32][33];
    const int bx = blockIdx.x * 32;
    const int by = blockIdx.y * 32;
    const int x = threadIdx.x, y = threadIdx.y;
    #pragma unroll
    for (int r = 0; r < 4; r++)
        t[y + r * 8][x] = W[(size_t)(by + y + r * 8) * EE + bx + x];
    __syncthreads();
    #pragma unroll
    for (int r = 0; r < 4; r++)
        Wt[(size_t)(bx + y + r * 8) * EE + by + x] = t[x][y + r * 8];
}

// ---------------------------------------------------------------------------
// HMMA tf32 GEMM (validated in R5): out = X[M,E] @ W + bias, Wt[n][k].
// ---------------------------------------------------------------------------
__global__ __launch_bounds__(256) void gemm_mma_kernel(
    const float* __restrict__ X, const float* __restrict__ Wt,
    const float* __restrict__ bias, float* __restrict__ out, int split)
{
    __shared__ float As[128][36];
    __shared__ float Bs[128][36];

    const int tid = threadIdx.x;
    const int wid = tid >> 5, lane = tid & 31;
    const int g = lane >> 2, t4 = lane & 3;
    const int wm = wid >> 2, wn = wid & 3;
    const int n0 = blockIdx.x * 128;
    const int m0 = blockIdx.y * 128;

    float c[4][4][4];
    #pragma unroll
    for (int mi = 0; mi < 4; mi++)
        #pragma unroll
        for (int ni = 0; ni < 4; ni++)
            #pragma unroll
            for (int e = 0; e < 4; e++) c[mi][ni][e] = 0.f;

    float4 Ar[4], Br[4];
    #pragma unroll
    for (int r = 0; r < 4; r++) {
        const int id = r * 256 + tid;
        const int row = id >> 3, c4 = id & 7;
        Ar[r] = *(const float4*)(X  + (size_t)(m0 + row) * EE + c4 * 4);
        Br[r] = *(const float4*)(Wt + (size_t)(n0 + row) * EE + c4 * 4);
    }

    for (int t = 0; t < EE / 32; t++) {
        #pragma unroll
        for (int r = 0; r < 4; r++) {
            const int id = r * 256 + tid;
            const int row = id >> 3, c4 = id & 7;
            float4 va = Ar[r];
            va.x = tf32r(va.x); va.y = tf32r(va.y); va.z = tf32r(va.z); va.w = tf32r(va.w);
            *(float4*)&As[row][c4 * 4] = va;
            float4 vb = Br[r];
            vb.x = tf32r(vb.x); vb.y = tf32r(vb.y); vb.z = tf32r(vb.z); vb.w = tf32r(vb.w);
            *(float4*)&Bs[row][c4 * 4] = vb;
        }
        __syncthreads();

        if (t + 1 < EE / 32) {
            const int k0 = (t + 1) * 32;
            #pragma unroll
            for (int r = 0; r < 4; r++) {
                const int id = r * 256 + tid;
                const int row = id >> 3, c4 = id & 7;
                Ar[r] = *(const float4*)(X  + (size_t)(m0 + row) * EE + k0 + c4 * 4);
                Br[r] = *(const float4*)(Wt + (size_t)(n0 + row) * EE + k0 + c4 * 4);
            }
        }

        #pragma unroll
        for (int kk = 0; kk < 32; kk += 8) {
            float a[4][4], b[4][2];
            #pragma unroll
            for (int mi = 0; mi < 4; mi++) {
                const int row = wm * 64 + mi * 16;
                a[mi][0] = As[row + g][kk + t4];
                a[mi][1] = As[row + g + 8][kk + t4];
                a[mi][2] = As[row + g][kk + t4 + 4];
                a[mi][3] = As[row + g + 8][kk + t4 + 4];
            }
            #pragma unroll
            for (int ni = 0; ni < 4; ni++) {
                const int col = wn * 32 + ni * 8 + g;
                b[ni][0] = Bs[col][kk + t4];
                b[ni][1] = Bs[col][kk + t4 + 4];
            }
            #pragma unroll
            for (int mi = 0; mi < 4; mi++)
                #pragma unroll
                for (int ni = 0; ni < 4; ni++)
                    MMA_TF32(c[mi][ni], a[mi], b[ni]);
        }
        __syncthreads();
    }

    #pragma unroll
    for (int mi = 0; mi < 4; mi++) {
        #pragma unroll
        for (int ni = 0; ni < 4; ni++) {
            const int r0 = m0 + wm * 64 + mi * 16 + g;
            const int cb = n0 + wn * 32 + ni * 8 + t4 * 2;
            const float bx = bias[cb], by = bias[cb + 1];
            #pragma unroll
            for (int half = 0; half < 2; half++) {
                const int r = r0 + half * 8;
                float2 v;
                v.x = c[mi][ni][half * 2 + 0] + bx;
                v.y = c[mi][ni][half * 2 + 1] + by;
                if (split) {
                    const int bbi = r >> 11, s = r & (SS - 1);
                    const int h = cb >> 6, d = cb & 63;
                    *(float2*)(out + ((size_t)(bbi * HH + h) * SS + s) * DHH + d) = v;
                } else {
                    *(float2*)(out + (size_t)r * EE + cb) = v;
                }
            }
        }
    }
}

// ---------------------------------------------------------------------------
// MMA flash attention: CTA = 128 q-rows of one (b,h); 64-key tiles.
// QK^T and P@V on tensor cores (tf32 mma.sync), smem online softmax.
// smem layout (floats, pad-68 rows): Qs[128][68] | Ks[64][68] | Vt[64][68]
//   | Ps[128][68] | m[128] | l[128] | sc[128] | mask[64]
// ---------------------------------------------------------------------------
#define AQ(r, cc)  sm[(r) * 68 + (cc)]
#define AK(r, cc)  sm[8704 + (r) * 68 + (cc)]
#define AV(d, kk)  sm[13056 + (d) * 68 + (kk)]
#define AP(r, cc)  sm[17408 + (r) * 68 + (cc)]
#define AM(r)      sm[26112 + (r)]
#define AL(r)      sm[26240 + (r)]
#define ASC(r)     sm[26368 + (r)]
#define AMK(kk)    ((int*)(sm + 26496))[(kk)]
#define ATTN_SMEM  (26560 * 4)

__global__ __launch_bounds__(256) void attn_mma_kernel(
    const int* __restrict__ mask, float* __restrict__ out)
{
    extern __shared__ float sm[];
    const int tid = threadIdx.x;
    const int wid = tid >> 5, lane = tid & 31;
    const int g = lane >> 2, t4 = lane & 3;
    const int wm = wid >> 2, wn = wid & 3;     // warps 2(m) x 4(n)
    const int bb = blockIdx.z, hh = blockIdx.y;
    const int q0 = blockIdx.x * 128;

    const float* Q = g_q + ((size_t)(bb * HH + hh) * SS) * DHH;
    const float* K = g_k + ((size_t)(bb * HH + hh) * SS) * DHH;
    const float* V = g_v + ((size_t)(bb * HH + hh) * SS) * DHH;

    // load Q tile (tf32-rounded): 128x64
    #pragma unroll
    for (int r = 0; r < 8; r++) {
        const int id = r * 256 + tid;
        const int row = id >> 4, c4 = id & 15;
        float4 v = *(const float4*)(Q + (size_t)(q0 + row) * DHH + c4 * 4);
        v.x = tf32r(v.x); v.y = tf32r(v.y); v.z = tf32r(v.z); v.w = tf32r(v.w);
        *(float4*)&AQ(row, c4 * 4) = v;
    }
    if (tid < 128) { AM(tid) = -1e30f; AL(tid) = 0.f; }

    float o[4][2][4];
    #pragma unroll
    for (int mi = 0; mi < 4; mi++)
        #pragma unroll
        for (int ni = 0; ni < 2; ni++)
            #pragma unroll
            for (int e = 0; e < 4; e++) o[mi][ni][e] = 0.f;
    __syncthreads();

    for (int kt = 0; kt < SS; kt += 64) {
        // load K (row-major, tf32) and V (transposed [d][key], tf32)
        #pragma unroll
        for (int r = 0; r < 4; r++) {
            const int id = r * 256 + tid;
            const int key = id >> 4, c4 = id & 15;
            float4 kv = *(const float4*)(K + (size_t)(kt + key) * DHH + c4 * 4);
            kv.x = tf32r(kv.x); kv.y = tf32r(kv.y); kv.z = tf32r(kv.z); kv.w = tf32r(kv.w);
            *(float4*)&AK(key, c4 * 4) = kv;
            float4 vv = *(const float4*)(V + (size_t)(kt + key) * DHH + c4 * 4);
            AV(c4 * 4 + 0, key) = tf32r(vv.x);
            AV(c4 * 4 + 1, key) = tf32r(vv.y);
            AV(c4 * 4 + 2, key) = tf32r(vv.z);
            AV(c4 * 4 + 3, key) = tf32r(vv.w);
        }
        if (tid < 64) AMK(tid) = mask[bb * SS + kt + tid];
        __syncthreads();

        // ---- scores = Q @ K^T : 128x64, warp tile 64x16 ----
        float c[4][2][4];
        #pragma unroll
        for (int mi = 0; mi < 4; mi++)
            #pragma unroll
            for (int ni = 0; ni < 2; ni++)
                #pragma unroll
                for (int e = 0; e < 4; e++) c[mi][ni][e] = 0.f;

        #pragma unroll
        for (int kk = 0; kk < 64; kk += 8) {
            float a[4][4], b[2][2];
            #pragma unroll
            for (int mi = 0; mi < 4; mi++) {
                const int row = wm * 64 + mi * 16;
                a[mi][0] = AQ(row + g, kk + t4);
                a[mi][1] = AQ(row + g + 8, kk + t4);
                a[mi][2] = AQ(row + g, kk + t4 + 4);
                a[mi][3] = AQ(row + g + 8, kk + t4 + 4);
            }
            #pragma unroll
            for (int ni = 0; ni < 2; ni++) {
                const int col = wn * 16 + ni * 8 + g;
                b[ni][0] = AK(col, kk + t4);
                b[ni][1] = AK(col, kk + t4 + 4);
            }
            #pragma unroll
            for (int mi = 0; mi < 4; mi++)
                #pragma unroll
                for (int ni = 0; ni < 2; ni++)
                    MMA_TF32(c[mi][ni], a[mi], b[ni]);
        }

        // scale + mask -> Ps
        #pragma unroll
        for (int mi = 0; mi < 4; mi++) {
            const int r0 = wm * 64 + mi * 16 + g;
            #pragma unroll
            for (int ni = 0; ni < 2; ni++) {
                const int cb = wn * 16 + ni * 8 + t4 * 2;
                const int mk0 = AMK(cb), mk1 = AMK(cb + 1);
                float v0 = c[mi][ni][0] * 0.125f, v1 = c[mi][ni][1] * 0.125f;
                float v2 = c[mi][ni][2] * 0.125f, v3 = c[mi][ni][3] * 0.125f;
                if (mk0 == 0) { v0 = -1e9f; v2 = -1e9f; }
                if (mk1 == 0) { v1 = -1e9f; v3 = -1e9f; }
                AP(r0, cb) = v0;     AP(r0, cb + 1) = v1;
                AP(r0 + 8, cb) = v2; AP(r0 + 8, cb + 1) = v3;
            }
        }
        __syncthreads();

        // ---- online softmax: 2 threads/row, 32 cols each ----
        {
            const int rrow = tid >> 1, half = tid & 1;
            float vals[32];
            float tmax = -1e30f;
            #pragma unroll
            for (int cc = 0; cc < 32; cc++) {
                vals[cc] = AP(rrow, half * 32 + cc);
                tmax = fmaxf(tmax, vals[cc]);
            }
            tmax = fmaxf(tmax, __shfl_xor_sync(0xffffffffu, tmax, 1));
            const float m_old = AM(rrow);
            const float m_new = fmaxf(m_old, tmax);
            float tsum = 0.f;
            #pragma unroll
            for (int cc = 0; cc < 32; cc++) {
                float p = tf32r(__expf(vals[cc] - m_new));
                AP(rrow, half * 32 + cc) = p;
                tsum += p;
            }
            tsum += __shfl_xor_sync(0xffffffffu, tsum, 1);
            if (half == 0) {
                const float sc = __expf(m_old - m_new);
                AL(rrow) = AL(rrow) * sc + tsum;
                AM(rrow) = m_new;
                ASC(rrow) = sc;
            }
        }
        __syncthreads();

        // rescale running output
        #pragma unroll
        for (int mi = 0; mi < 4; mi++) {
            const int r0 = wm * 64 + mi * 16 + g;
            const float s0 = ASC(r0), s1 = ASC(r0 + 8);
            #pragma unroll
            for (int ni = 0; ni < 2; ni++) {
                o[mi][ni][0] *= s0; o[mi][ni][1] *= s0;
                o[mi][ni][2] *= s1; o[mi][ni][3] *= s1;
            }
        }

        // ---- O += P @ V : A=Ps[128][64keys], B=Vt[d][key] ----
        #pragma unroll
        for (int kk = 0; kk < 64; kk += 8) {
            float a[4][4], b[2][2];
            #pragma unroll
            for (int mi = 0; mi < 4; mi++) {
                const int row = wm * 64 + mi * 16;
                a[mi][0] = AP(row + g, kk + t4);
                a[mi][1] = AP(row + g + 8, kk + t4);
                a[mi][2] = AP(row + g, kk + t4 + 4);
                a[mi][3] = AP(row + g + 8, kk + t4 + 4);
            }
            #pragma unroll
            for (int ni = 0; ni < 2; ni++) {
                const int col = wn * 16 + ni * 8 + g;   // d index
                b[ni][0] = AV(col, kk + t4);
                b[ni][1] = AV(col, kk + t4 + 4);
            }
            #pragma unroll
            for (int mi = 0; mi < 4; mi++)
                #pragma unroll
                for (int ni = 0; ni < 2; ni++)
                    MMA_TF32(o[mi][ni], a[mi], b[ni]);
        }
        __syncthreads();
    }

    // finalize: divide by l, write merged-heads [B,S,E]
    #pragma unroll
    for (int mi = 0; mi < 4; mi++) {
        const int r0 = wm * 64 + mi * 16 + g;
        const float li0 = 1.0f / AL(r0), li1 = 1.0f / AL(r0 + 8);
        #pragma unroll
        for (int ni = 0; ni < 2; ni++) {
            const int cb = wn * 16 + ni * 8 + t4 * 2;
            float2 v;
            v.x = o[mi][ni][0] * li0; v.y = o[mi][ni][1] * li0;
            *(float2*)(out + (size_t)(bb * SS + q0 + r0) * EE + hh * DHH + cb) = v;
            v.x = o[mi][ni][2] * li1; v.y = o[mi][ni][3] * li1;
            *(float2*)(out + (size_t)(bb * SS + q0 + r0 + 8) * EE + hh * DHH + cb) = v;
        }
    }
}

// ---------------------------------------------------------------------------
extern "C" void kernel_launch(void* const* d_in, const int* in_sizes, int n_in,
                              void* d_out, int out_size)
{
    const float* query = (const float*)d_in[0];
    const float* key   = (const float*)d_in[1];
    const float* value = (const float*)d_in[2];
    const int*   mask  = (const int*)  d_in[3];
    const float* Wq = (const float*)d_in[4];
    const float* bq = (const float*)d_in[5];
    const float* Wk = (const float*)d_in[6];
    const float* bk = (const float*)d_in[7];
    const float* Wv = (const float*)d_in[8];
    const float* bv = (const float*)d_in[9];
    const float* Wo = (const float*)d_in[10];
    const float* bo = (const float*)d_in[11];
    float* out = (float*)d_out;

    float *gq, *gk, *gv, *ga, *gw;
    cudaGetSymbolAddress((void**)&gq, g_q);
    cudaGetSymbolAddress((void**)&gk, g_k);
    cudaGetSymbolAddress((void**)&gv, g_v);
    cudaGetSymbolAddress((void**)&ga, g_attn);
    cudaGetSymbolAddress((void**)&gw, g_wt);

    cudaFuncSetAttribute(attn_mma_kernel,
                         cudaFuncAttributeMaxDynamicSharedMemorySize, ATTN_SMEM);

    dim3 tgrid(EE / 32, EE / 32);
    dim3 tblk(32, 8);
    transpose_kernel<<<tgrid, tblk>>>(Wq, gw + 0 * (size_t)EE * EE);
    transpose_kernel<<<tgrid, tblk>>>(Wk, gw + 1 * (size_t)EE * EE);
    transpose_kernel<<<tgrid, tblk>>>(Wv, gw + 2 * (size_t)EE * EE);
    transpose_kernel<<<tgrid, tblk>>>(Wo, gw + 3 * (size_t)EE * EE);

    dim3 ggrid(EE / 128, MM / 128);    // (8, 32)
    gemm_mma_kernel<<<ggrid, 256>>>(query, gw + 0 * (size_t)EE * EE, bq, gq, 1);
    gemm_mma_kernel<<<ggrid, 256>>>(key,   gw + 1 * (size_t)EE * EE, bk, gk, 1);
    gemm_mma_kernel<<<ggrid, 256>>>(value, gw + 2 * (size_t)EE * EE, bv, gv, 1);

    dim3 agrid(SS / 128, HH, BB);      // (16, 16, 2)
    attn_mma_kernel<<<agrid, 256, ATTN_SMEM>>>(mask, ga);

    gemm_mma_kernel<<<ggrid, 256>>>(ga, gw + 3 * (size_t)EE * EE, bo, out, 0);
}